// round 12
// baseline (speedup 1.0000x reference)
#include <cuda_runtime.h>
#include <cstdint>

// Problem constants (fixed by the reference).
#define N_IN      262144         // INPUT_LAYER
#define HIDDEN    3
#define LAYERS    120
#define NCHAIN    (LAYERS - 1)   // 119
#define OUTPUTS   18

#define PROD      128            // all blocks produce; last one runs the tail
#define THREADS   256
#define POS_PER_BLOCK 512        // float4 positions per block (65536/128)
#define CHUNK_BYTES   (POS_PER_BLOCK * 16)   // 8192 per array per block

// Scratch (no allocations allowed).
__device__ float4   g_part4[PROD];   // per-block partials {s0,s1,s2,0}
__device__ unsigned g_count;         // zero at load; reset by the winner

// HW tanh: MUFU.TANH, ~16cyc.
__device__ __forceinline__ float tanh_hw(float t) {
    float h;
    asm("tanh.approx.f32 %0, %1;" : "=f"(h) : "f"(t));
    return h;
}

__device__ __forceinline__ uint32_t smem_u32(const void* p) {
    uint32_t a;
    asm("{ .reg .u64 t; cvta.to.shared.u64 t, %1; cvt.u32.u64 %0, t; }"
        : "=r"(a) : "l"(p));
    return a;
}

__global__ __launch_bounds__(THREADS, 1)
void dqn_fused_kernel(const float* __restrict__ x,
                      const float* __restrict__ W0,     // (3, 262144)
                      const float* __restrict__ bih0,   // (3,)
                      const float* __restrict__ bhh0,   // (3,)
                      const float* __restrict__ Wl,     // (119, 3, 3)
                      const float* __restrict__ bil,    // (119, 3)
                      const float* __restrict__ bhl,    // (119, 3)
                      const float* __restrict__ Wh,     // (18, 120)
                      const float* __restrict__ bh,     // (18,)
                      float* __restrict__ out)          // (3, 18)
{
    // TMA staging (8KB x 4 = 32KB)
    __shared__ float4 sX [POS_PER_BLOCK];
    __shared__ float4 sW0[POS_PER_BLOCK];
    __shared__ float4 sW1[POS_PER_BLOCK];
    __shared__ float4 sW2[POS_PER_BLOCK];
    // Tail data, preloaded by EVERY block (L2-amortized ~13KB) so whichever
    // block finishes last can run the chain with zero handoff.
    __shared__ float4 sP2[NCHAIN * 3 + 3];       // 12 floats/layer + pad
    __shared__ float  sWhT[LAYERS * OUTPUTS];    // transposed head [l][o]
    __shared__ float  sB0[3];                    // layer-0 fused bias
    __shared__ float  sBh[OUTPUTS];
    __shared__ float  wsum[3][8];
    __shared__ __align__(8) unsigned long long mbar;

    const int tid = threadIdx.x;
    const int pid = blockIdx.x;
    const uint32_t mb = smem_u32(&mbar);

    // ---- mbarrier init (fresh each launch -> phase 0) ----------------------
    if (tid == 0) {
        asm volatile("mbarrier.init.shared.b64 [%0], 1;" :: "r"(mb) : "memory");
    }
    __syncthreads();

    // ---- Issue 4 bulk copies: x slice + 3 W0-row slices --------------------
    if (tid == 0) {
        asm volatile("fence.proxy.async.shared::cta;" ::: "memory");
        asm volatile("mbarrier.arrive.expect_tx.shared.b64 _, [%0], %1;"
                     :: "r"(mb), "r"(4u * CHUNK_BYTES) : "memory");
        const char* srcx = (const char*)x             + (size_t)pid * CHUNK_BYTES;
        const char* s0   = (const char*)W0            + (size_t)pid * CHUNK_BYTES;
        const char* s1   = (const char*)(W0 + N_IN)   + (size_t)pid * CHUNK_BYTES;
        const char* s2   = (const char*)(W0 + 2*N_IN) + (size_t)pid * CHUNK_BYTES;
        asm volatile("cp.async.bulk.shared::cluster.global.mbarrier::complete_tx::bytes [%0], [%1], %2, [%3];"
                     :: "r"(smem_u32(sX)),  "l"(srcx), "r"((uint32_t)CHUNK_BYTES), "r"(mb) : "memory");
        asm volatile("cp.async.bulk.shared::cluster.global.mbarrier::complete_tx::bytes [%0], [%1], %2, [%3];"
                     :: "r"(smem_u32(sW0)), "l"(s0),   "r"((uint32_t)CHUNK_BYTES), "r"(mb) : "memory");
        asm volatile("cp.async.bulk.shared::cluster.global.mbarrier::complete_tx::bytes [%0], [%1], %2, [%3];"
                     :: "r"(smem_u32(sW1)), "l"(s1),   "r"((uint32_t)CHUNK_BYTES), "r"(mb) : "memory");
        asm volatile("cp.async.bulk.shared::cluster.global.mbarrier::complete_tx::bytes [%0], [%1], %2, [%3];"
                     :: "r"(smem_u32(sW2)), "l"(s2),   "r"((uint32_t)CHUNK_BYTES), "r"(mb) : "memory");
    }

    // ---- Preload chain/head weights while the TMA flies (L2-amortized) -----
    {
        float* sPf = reinterpret_cast<float*>(sP2);
        for (int i = tid; i < NCHAIN * 12; i += THREADS) {
            const int l = i / 12, k = i - l * 12;
            sPf[i] = (k < 9) ? Wl[l * 9 + k]
                             : bil[l * 3 + (k - 9)] + bhl[l * 3 + (k - 9)];
        }
        if (tid < 12) sPf[NCHAIN * 12 + tid] = 0.f;       // pad layer
        for (int i = tid; i < LAYERS * OUTPUTS; i += THREADS) {
            const int l = i / OUTPUTS, o = i - l * OUTPUTS;
            sWhT[i] = Wh[o * LAYERS + l];
        }
        if (tid < 3)       sB0[tid] = bih0[tid] + bhh0[tid];
        if (tid < OUTPUTS) sBh[tid] = bh[tid];
    }

    // ---- Wait for the bulk copies (acquire) --------------------------------
    asm volatile(
        "{\n\t"
        ".reg .pred p;\n\t"
        "W%=:\n\t"
        "mbarrier.try_wait.parity.acquire.cta.shared::cta.b64 p, [%0], 0;\n\t"
        "@!p bra W%=;\n\t"
        "}" :: "r"(mb) : "memory");

    // ---- Dot products out of shared (2 positions per thread) ---------------
    float s0, s1, s2;
    {
        const int q0 = tid, q1 = tid + THREADS;
        const float4 xa = sX[q0],  xb = sX[q1];
        const float4 a0 = sW0[q0], b0 = sW0[q1];
        const float4 a1 = sW1[q0], b1 = sW1[q1];
        const float4 a2 = sW2[q0], b2 = sW2[q1];
        s0 = a0.x*xa.x + a0.y*xa.y + a0.z*xa.z + a0.w*xa.w
           + b0.x*xb.x + b0.y*xb.y + b0.z*xb.z + b0.w*xb.w;
        s1 = a1.x*xa.x + a1.y*xa.y + a1.z*xa.z + a1.w*xa.w
           + b1.x*xb.x + b1.y*xb.y + b1.z*xb.z + b1.w*xb.w;
        s2 = a2.x*xa.x + a2.y*xa.y + a2.z*xa.z + a2.w*xa.w
           + b2.x*xb.x + b2.y*xb.y + b2.z*xb.z + b2.w*xb.w;
    }
    #pragma unroll
    for (int off = 16; off > 0; off >>= 1) {
        s0 += __shfl_down_sync(0xFFFFFFFFu, s0, off);
        s1 += __shfl_down_sync(0xFFFFFFFFu, s1, off);
        s2 += __shfl_down_sync(0xFFFFFFFFu, s2, off);
    }
    const int wid = tid >> 5, lid = tid & 31;
    if (lid == 0) { wsum[0][wid] = s0; wsum[1][wid] = s1; wsum[2][wid] = s2; }
    __syncthreads();   // also makes sP2/sWhT/sB0/sBh visible block-wide

    // ---- Publish partial + acq_rel increment; last arriver wins ------------
    int won = 0;
    if (tid == 0) {
        float b0 = 0.f, b1 = 0.f, b2 = 0.f;
        #pragma unroll
        for (int w = 0; w < 8; ++w) {
            b0 += wsum[0][w]; b1 += wsum[1][w]; b2 += wsum[2][w];
        }
        __stcg(&g_part4[pid], make_float4(b0, b1, b2, 0.f));
        unsigned prev, one = 1u;
        asm volatile("atom.acq_rel.gpu.global.add.u32 %0, [%1], %2;"
                     : "=r"(prev) : "l"(&g_count), "r"(one) : "memory");
        won = (prev == PROD - 1);
    }
    // Only warp 0 can win (tid0 is its lane 0); broadcast the flag.
    if (tid >= 32) return;
    won = __shfl_sync(0xFFFFFFFFu, won, 0);
    if (!won) return;

    // ======================= Winner warp: tail ==============================
    const int lane = tid;
    if (lane == 0) g_count = 0;          // ready for next graph replay

    // Gather 128 partials, 4/lane, fixed order (deterministic regardless of
    // which block won). The acq_rel atomic ordered all released stores.
    float r0 = 0.f, r1 = 0.f, r2 = 0.f;
    #pragma unroll
    for (int k = 0; k < 4; ++k) {
        const float4 a = __ldcg(&g_part4[lane * 4 + k]);
        r0 += a.x; r1 += a.y; r2 += a.z;
    }
    #pragma unroll
    for (int off = 16; off > 0; off >>= 1) {
        r0 += __shfl_down_sync(0xFFFFFFFFu, r0, off);
        r1 += __shfl_down_sync(0xFFFFFFFFu, r1, off);
        r2 += __shfl_down_sync(0xFFFFFFFFu, r2, off);
    }
    r0 = __shfl_sync(0xFFFFFFFFu, r0, 0);
    r1 = __shfl_sync(0xFFFFFFFFu, r1, 0);
    r2 = __shfl_sync(0xFFFFFFFFu, r2, 0);

    // Per-lane head outputs: p0=lane, p1=lane+27 (lanes < 27).
    const int p0 = (lane < 27) ? lane : 0;
    const int j0 = p0 / OUTPUTS, o0 = p0 - j0 * OUTPUTS;   // j0 in {0,1}
    const int p1 = p0 + 27;
    const int j1 = p1 / OUTPUTS, o1 = p1 - j1 * OUTPUTS;   // j1 in {1,2}

    // Layer 0 (all lanes redundantly; no cross-lane dependency).
    float h0 = tanh_hw(r0 + sB0[0]);
    float h1 = tanh_hw(r1 + sB0[1]);
    float h2 = tanh_hw(r2 + sB0[2]);

    float acc0 = 0.f, acc1 = 0.f;
    float4 c0 = sP2[0], c1 = sP2[1], c2 = sP2[2];

    // 119 layers @ ~28-34cyc: 3-FMA dot (12) + MUFU.TANH (16).
    // Prefetch + head FMAs ride in the dependency bubble.
    // Packing: c0={w00,w01,w02,w10} c1={w11,w12,w20,w21} c2={w22,b0,b1,b2}
    #pragma unroll 7
    for (int l = 1; l <= NCHAIN; ++l) {
        const float4 n0 = sP2[l * 3 + 0];     // next layer (pad-safe)
        const float4 n1 = sP2[l * 3 + 1];
        const float4 n2 = sP2[l * 3 + 2];
        // Head contribution of H[l-1] (current h regs).
        const float ha = (j0 == 0) ? h0 : h1;
        const float hb = (j1 == 1) ? h1 : h2;
        acc0 = fmaf(ha, sWhT[(l - 1) * OUTPUTS + o0], acc0);
        acc1 = fmaf(hb, sWhT[(l - 1) * OUTPUTS + o1], acc1);
        // Chain step.
        const float t0 = fmaf(c0.x, h0, fmaf(c0.y, h1, fmaf(c0.z, h2, c2.y)));
        const float t1 = fmaf(c0.w, h0, fmaf(c1.x, h1, fmaf(c1.y, h2, c2.z)));
        const float t2 = fmaf(c1.z, h0, fmaf(c1.w, h1, fmaf(c2.x, h2, c2.w)));
        h0 = tanh_hw(t0);
        h1 = tanh_hw(t1);
        h2 = tanh_hw(t2);
        c0 = n0; c1 = n1; c2 = n2;
    }

    // Final layer's H into the head, then write.
    const float ha = (j0 == 0) ? h0 : h1;
    const float hb = (j1 == 1) ? h1 : h2;
    acc0 = fmaf(ha, sWhT[NCHAIN * OUTPUTS + o0], acc0);
    acc1 = fmaf(hb, sWhT[NCHAIN * OUTPUTS + o1], acc1);

    if (lane < 27) {
        out[j0 * OUTPUTS + o0] = acc0 + sBh[o0];
        out[j1 * OUTPUTS + o1] = acc1 + sBh[o1];
    }
}

extern "C" void kernel_launch(void* const* d_in, const int* in_sizes, int n_in,
                              void* d_out, int out_size) {
    const float* x    = (const float*)d_in[0];
    const float* W0   = (const float*)d_in[1];
    const float* bih0 = (const float*)d_in[2];
    const float* bhh0 = (const float*)d_in[3];
    const float* Wl   = (const float*)d_in[4];
    const float* bil  = (const float*)d_in[5];
    const float* bhl  = (const float*)d_in[6];
    const float* Wh   = (const float*)d_in[7];
    const float* bh   = (const float*)d_in[8];
    float* out        = (float*)d_out;

    dqn_fused_kernel<<<PROD, THREADS>>>(x, W0, bih0, bhh0,
                                        Wl, bil, bhl, Wh, bh, out);
}

// round 14
// speedup vs baseline: 1.1222x; 1.1222x over previous
#include <cuda_runtime.h>
#include <cstdint>

// Problem constants (fixed by the reference).
#define N_IN      262144         // INPUT_LAYER
#define HIDDEN    3
#define LAYERS    120
#define NCHAIN    (LAYERS - 1)   // 119
#define OUTPUTS   18

#define PROD      128            // producer blocks (blocks 1..128)
#define GRID      (PROD + 1)     // + tail block 0; single wave (129 <= 148)
#define THREADS   256
#define POS_PER_BLOCK 512        // float4 positions per producer (65536/128)
#define CHUNK_BYTES   (POS_PER_BLOCK * 16)   // 8192 per array per producer

// Scratch (no allocations allowed).
__device__ float4   g_part4[PROD];   // per-producer partials {s0,s1,s2,0}
__device__ unsigned g_count;         // zero at load; reset by tail block

// HW tanh: MUFU.TANH, ~16cyc.
__device__ __forceinline__ float tanh_hw(float t) {
    float h;
    asm("tanh.approx.f32 %0, %1;" : "=f"(h) : "f"(t));
    return h;
}

__device__ __forceinline__ uint32_t smem_u32(const void* p) {
    uint32_t a;
    asm("{ .reg .u64 t; cvta.to.shared.u64 t, %1; cvt.u32.u64 %0, t; }"
        : "=r"(a) : "l"(p));
    return a;
}

__global__ __launch_bounds__(THREADS, 1)
void dqn_fused_kernel(const float* __restrict__ x,
                      const float* __restrict__ W0,     // (3, 262144)
                      const float* __restrict__ bih0,   // (3,)
                      const float* __restrict__ bhh0,   // (3,)
                      const float* __restrict__ Wl,     // (119, 3, 3)
                      const float* __restrict__ bil,    // (119, 3)
                      const float* __restrict__ bhl,    // (119, 3)
                      const float* __restrict__ Wh,     // (18, 120)
                      const float* __restrict__ bh,     // (18,)
                      float* __restrict__ out)          // (3, 18)
{
    // TMA staging for producers (8KB x 4 = 32KB)
    __shared__ float4 sX [POS_PER_BLOCK];
    __shared__ float4 sW0[POS_PER_BLOCK];
    __shared__ float4 sW1[POS_PER_BLOCK];
    __shared__ float4 sW2[POS_PER_BLOCK];
    // Tail-block data
    __shared__ float4 sP2[NCHAIN * 3 + 3];       // 12 floats/layer + pad
    __shared__ float  sWhT[LAYERS * OUTPUTS];    // transposed head [l][o]
    __shared__ float  sB0[3];                    // layer-0 fused bias
    __shared__ float  sBh[OUTPUTS];
    __shared__ float  wsum[3][8];
    __shared__ __align__(8) unsigned long long mbar;

    const int tid = threadIdx.x;
    const int bid = blockIdx.x;

    // ======================= Tail block (bid == 0) ==========================
    if (bid == 0) {
        // ---- Preload + repack (fully overlaps producers' TMA phase) -------
        float* sPf = reinterpret_cast<float*>(sP2);
        for (int i = tid; i < NCHAIN * 12; i += THREADS) {
            const int l = i / 12, k = i - l * 12;
            sPf[i] = (k < 9) ? Wl[l * 9 + k]
                             : bil[l * 3 + (k - 9)] + bhl[l * 3 + (k - 9)];
        }
        if (tid < 12) sPf[NCHAIN * 12 + tid] = 0.f;       // pad layer
        for (int i = tid; i < LAYERS * OUTPUTS; i += THREADS) {
            const int l = i / OUTPUTS, o = i - l * OUTPUTS;
            sWhT[i] = Wh[o * LAYERS + l];
        }
        if (tid < 3)       sB0[tid] = bih0[tid] + bhh0[tid];
        if (tid < OUTPUTS) sBh[tid] = bh[tid];
        __syncthreads();                 // smem visible to warp 0
        if (tid >= 32) return;           // only warp 0 continues

        const int lane = tid;

        // ---- All 32 lanes spin on the counter (each gets acquire) ---------
        unsigned v;
        do {
            asm volatile("ld.acquire.gpu.global.u32 %0, [%1];"
                         : "=r"(v) : "l"(&g_count));
        } while (v < PROD);
        if (lane == 0) g_count = 0;      // ready for next graph replay

        // ---- Gather 128 partials, 4/lane, fixed order (deterministic) -----
        float r0 = 0.f, r1 = 0.f, r2 = 0.f;
        #pragma unroll
        for (int k = 0; k < 4; ++k) {
            const float4 a = __ldcg(&g_part4[lane * 4 + k]);
            r0 += a.x; r1 += a.y; r2 += a.z;
        }
        #pragma unroll
        for (int off = 16; off > 0; off >>= 1) {
            r0 += __shfl_down_sync(0xFFFFFFFFu, r0, off);
            r1 += __shfl_down_sync(0xFFFFFFFFu, r1, off);
            r2 += __shfl_down_sync(0xFFFFFFFFu, r2, off);
        }
        r0 = __shfl_sync(0xFFFFFFFFu, r0, 0);
        r1 = __shfl_sync(0xFFFFFFFFu, r1, 0);
        r2 = __shfl_sync(0xFFFFFFFFu, r2, 0);

        // Per-lane head outputs: p0=lane, p1=lane+27 (lanes < 27).
        const int p0 = (lane < 27) ? lane : 0;
        const int j0 = p0 / OUTPUTS, o0 = p0 - j0 * OUTPUTS;   // j0 in {0,1}
        const int p1 = p0 + 27;
        const int j1 = p1 / OUTPUTS, o1 = p1 - j1 * OUTPUTS;   // j1 in {1,2}

        // ---- Layer 0 (all lanes redundantly; no cross-lane dependency) ----
        float h0 = tanh_hw(r0 + sB0[0]);
        float h1 = tanh_hw(r1 + sB0[1]);
        float h2 = tanh_hw(r2 + sB0[2]);

        float acc0 = 0.f, acc1 = 0.f;
        float4 c0 = sP2[0], c1 = sP2[1], c2 = sP2[2];

        // ---- 119 layers. MUFU results arrive staggered (h0 first, h2 ~16cyc
        // later), so the FMA tree consumes h0 INNERMOST: the tree starts the
        // moment h0 lands and h1/h2 slot into later levels just in time.
        // Packing: c0={w00,w01,w02,w10} c1={w11,w12,w20,w21} c2={w22,b0,b1,b2}
        #pragma unroll 7
        for (int l = 1; l <= NCHAIN; ++l) {
            const float4 n0 = sP2[l * 3 + 0];     // next layer (pad-safe)
            const float4 n1 = sP2[l * 3 + 1];
            const float4 n2 = sP2[l * 3 + 2];
            // Head contribution of H[l-1] (current h regs) in the bubble.
            const float ha = (j0 == 0) ? h0 : h1;
            const float hb = (j1 == 1) ? h1 : h2;
            acc0 = fmaf(ha, sWhT[(l - 1) * OUTPUTS + o0], acc0);
            acc1 = fmaf(hb, sWhT[(l - 1) * OUTPUTS + o1], acc1);
            // Chain step: h0 innermost, h2 outermost (latency-ordered).
            const float t0 = fmaf(c0.z, h2, fmaf(c0.y, h1, fmaf(c0.x, h0, c2.y)));
            const float t1 = fmaf(c1.y, h2, fmaf(c1.x, h1, fmaf(c0.w, h0, c2.z)));
            const float t2 = fmaf(c2.x, h2, fmaf(c1.w, h1, fmaf(c1.z, h0, c2.w)));
            h0 = tanh_hw(t0);
            h1 = tanh_hw(t1);
            h2 = tanh_hw(t2);
            c0 = n0; c1 = n1; c2 = n2;
        }

        // ---- Final layer's H into the head, then write -------------------
        const float ha = (j0 == 0) ? h0 : h1;
        const float hb = (j1 == 1) ? h1 : h2;
        acc0 = fmaf(ha, sWhT[NCHAIN * OUTPUTS + o0], acc0);
        acc1 = fmaf(hb, sWhT[NCHAIN * OUTPUTS + o1], acc1);

        if (lane < 27) {
            out[j0 * OUTPUTS + o0] = acc0 + sBh[o0];
            out[j1 * OUTPUTS + o1] = acc1 + sBh[o1];
        }
        return;
    }

    // ======================= Producer blocks (bid 1..128) ===================
    const int pid = bid - 1;
    const uint32_t mb = smem_u32(&mbar);

    if (tid == 0) {
        asm volatile("mbarrier.init.shared.b64 [%0], 1;" :: "r"(mb) : "memory");
    }
    __syncthreads();

    if (tid == 0) {
        asm volatile("fence.proxy.async.shared::cta;" ::: "memory");
        asm volatile("mbarrier.arrive.expect_tx.shared.b64 _, [%0], %1;"
                     :: "r"(mb), "r"(4u * CHUNK_BYTES) : "memory");
        const char* srcx = (const char*)x             + (size_t)pid * CHUNK_BYTES;
        const char* s0   = (const char*)W0            + (size_t)pid * CHUNK_BYTES;
        const char* s1   = (const char*)(W0 + N_IN)   + (size_t)pid * CHUNK_BYTES;
        const char* s2   = (const char*)(W0 + 2*N_IN) + (size_t)pid * CHUNK_BYTES;
        asm volatile("cp.async.bulk.shared::cluster.global.mbarrier::complete_tx::bytes [%0], [%1], %2, [%3];"
                     :: "r"(smem_u32(sX)),  "l"(srcx), "r"((uint32_t)CHUNK_BYTES), "r"(mb) : "memory");
        asm volatile("cp.async.bulk.shared::cluster.global.mbarrier::complete_tx::bytes [%0], [%1], %2, [%3];"
                     :: "r"(smem_u32(sW0)), "l"(s0),   "r"((uint32_t)CHUNK_BYTES), "r"(mb) : "memory");
        asm volatile("cp.async.bulk.shared::cluster.global.mbarrier::complete_tx::bytes [%0], [%1], %2, [%3];"
                     :: "r"(smem_u32(sW1)), "l"(s1),   "r"((uint32_t)CHUNK_BYTES), "r"(mb) : "memory");
        asm volatile("cp.async.bulk.shared::cluster.global.mbarrier::complete_tx::bytes [%0], [%1], %2, [%3];"
                     :: "r"(smem_u32(sW2)), "l"(s2),   "r"((uint32_t)CHUNK_BYTES), "r"(mb) : "memory");
    }

    // Wait for the bulk copies (acquire).
    asm volatile(
        "{\n\t"
        ".reg .pred p;\n\t"
        "W%=:\n\t"
        "mbarrier.try_wait.parity.acquire.cta.shared::cta.b64 p, [%0], 0;\n\t"
        "@!p bra W%=;\n\t"
        "}" :: "r"(mb) : "memory");

    // Dot products out of shared (2 positions per thread).
    float s0, s1, s2;
    {
        const int q0 = tid, q1 = tid + THREADS;
        const float4 xa = sX[q0],  xb = sX[q1];
        const float4 a0 = sW0[q0], b0 = sW0[q1];
        const float4 a1 = sW1[q0], b1 = sW1[q1];
        const float4 a2 = sW2[q0], b2 = sW2[q1];
        s0 = a0.x*xa.x + a0.y*xa.y + a0.z*xa.z + a0.w*xa.w
           + b0.x*xb.x + b0.y*xb.y + b0.z*xb.z + b0.w*xb.w;
        s1 = a1.x*xa.x + a1.y*xa.y + a1.z*xa.z + a1.w*xa.w
           + b1.x*xb.x + b1.y*xb.y + b1.z*xb.z + b1.w*xb.w;
        s2 = a2.x*xa.x + a2.y*xa.y + a2.z*xa.z + a2.w*xa.w
           + b2.x*xb.x + b2.y*xb.y + b2.z*xb.z + b2.w*xb.w;
    }
    #pragma unroll
    for (int off = 16; off > 0; off >>= 1) {
        s0 += __shfl_down_sync(0xFFFFFFFFu, s0, off);
        s1 += __shfl_down_sync(0xFFFFFFFFu, s1, off);
        s2 += __shfl_down_sync(0xFFFFFFFFu, s2, off);
    }
    const int wid = tid >> 5, lid = tid & 31;
    if (lid == 0) { wsum[0][wid] = s0; wsum[1][wid] = s1; wsum[2][wid] = s2; }
    __syncthreads();

    if (tid == 0) {
        float b0 = 0.f, b1 = 0.f, b2 = 0.f;
        #pragma unroll
        for (int w = 0; w < 8; ++w) {
            b0 += wsum[0][w]; b1 += wsum[1][w]; b2 += wsum[2][w];
        }
        __stcg(&g_part4[pid], make_float4(b0, b1, b2, 0.f));
        unsigned one = 1u;
        asm volatile("red.release.gpu.global.add.u32 [%0], %1;"
                     :: "l"(&g_count), "r"(one) : "memory");
    }
}

extern "C" void kernel_launch(void* const* d_in, const int* in_sizes, int n_in,
                              void* d_out, int out_size) {
    const float* x    = (const float*)d_in[0];
    const float* W0   = (const float*)d_in[1];
    const float* bih0 = (const float*)d_in[2];
    const float* bhh0 = (const float*)d_in[3];
    const float* Wl   = (const float*)d_in[4];
    const float* bil  = (const float*)d_in[5];
    const float* bhl  = (const float*)d_in[6];
    const float* Wh   = (const float*)d_in[7];
    const float* bh   = (const float*)d_in[8];
    float* out        = (float*)d_out;

    dqn_fused_kernel<<<GRID, THREADS>>>(x, W0, bih0, bhh0,
                                        Wl, bil, bhl, Wh, bh, out);
}

// round 15
// speedup vs baseline: 1.1318x; 1.0086x over previous
#include <cuda_runtime.h>
#include <cstdint>

// Problem constants (fixed by the reference).
#define N_IN      262144         // INPUT_LAYER
#define HIDDEN    3
#define LAYERS    120
#define NCHAIN    (LAYERS - 1)   // 119
#define OUTPUTS   18

#define PROD      128            // producer blocks (blocks 1..128)
#define GRID      (PROD + 1)     // + tail block 0; single wave (129 <= 148)
#define THREADS   256
#define POS_PER_BLOCK 512        // float4 positions per producer (65536/128)
#define CHUNK_BYTES   (POS_PER_BLOCK * 16)   // 8192 per array per producer

// Scratch (no allocations allowed). Zero-initialized at module load.
// Each slot: {s0, s1, s2, flag} — flag=1.0f marks "valid this replay".
// The tail resets flags to 0 after consuming (replays are stream-ordered).
__device__ float4 g_part4[PROD];

// HW tanh: MUFU.TANH, ~16cyc.
__device__ __forceinline__ float tanh_hw(float t) {
    float h;
    asm("tanh.approx.f32 %0, %1;" : "=f"(h) : "f"(t));
    return h;
}

__device__ __forceinline__ uint32_t smem_u32(const void* p) {
    uint32_t a;
    asm("{ .reg .u64 t; cvta.to.shared.u64 t, %1; cvt.u32.u64 %0, t; }"
        : "=r"(a) : "l"(p));
    return a;
}

__global__ __launch_bounds__(THREADS, 1)
void dqn_fused_kernel(const float* __restrict__ x,
                      const float* __restrict__ W0,     // (3, 262144)
                      const float* __restrict__ bih0,   // (3,)
                      const float* __restrict__ bhh0,   // (3,)
                      const float* __restrict__ Wl,     // (119, 3, 3)
                      const float* __restrict__ bil,    // (119, 3)
                      const float* __restrict__ bhl,    // (119, 3)
                      const float* __restrict__ Wh,     // (18, 120)
                      const float* __restrict__ bh,     // (18,)
                      float* __restrict__ out)          // (3, 18)
{
    // TMA staging for producers (8KB x 4 = 32KB)
    __shared__ float4 sX [POS_PER_BLOCK];
    __shared__ float4 sW0[POS_PER_BLOCK];
    __shared__ float4 sW1[POS_PER_BLOCK];
    __shared__ float4 sW2[POS_PER_BLOCK];
    // Tail-block data
    __shared__ float4 sP2[NCHAIN * 3 + 3];       // 12 floats/layer + pad
    __shared__ float  sWhT[LAYERS * OUTPUTS];    // transposed head [l][o]
    __shared__ float  sB0[3];                    // layer-0 fused bias
    __shared__ float  sBh[OUTPUTS];
    __shared__ float  wsum[3][8];
    __shared__ __align__(8) unsigned long long mbar;

    const int tid = threadIdx.x;
    const int bid = blockIdx.x;

    // ======================= Tail block (bid == 0) ==========================
    if (bid == 0) {
        // ---- Preload + repack (fully overlaps producers' TMA phase) -------
        float* sPf = reinterpret_cast<float*>(sP2);
        for (int i = tid; i < NCHAIN * 12; i += THREADS) {
            const int l = i / 12, k = i - l * 12;
            sPf[i] = (k < 9) ? Wl[l * 9 + k]
                             : bil[l * 3 + (k - 9)] + bhl[l * 3 + (k - 9)];
        }
        if (tid < 12) sPf[NCHAIN * 12 + tid] = 0.f;       // pad layer
        for (int i = tid; i < LAYERS * OUTPUTS; i += THREADS) {
            const int l = i / OUTPUTS, o = i - l * OUTPUTS;
            sWhT[i] = Wh[o * LAYERS + l];
        }
        if (tid < 3)       sB0[tid] = bih0[tid] + bhh0[tid];
        if (tid < OUTPUTS) sBh[tid] = bh[tid];
        __syncthreads();                 // smem visible to warp 0
        if (tid >= 32) return;           // only warp 0 continues

        const int lane = tid;

        // ---- Gather: each lane polls its own 4 slots directly. The 16B
        //      producer store is a single transaction, so flag+data arrive
        //      atomically — no counter, no fence, no acquire needed.
        //      Fixed slot order (k=0..3, lane-major in the later shuffle)
        //      -> bitwise deterministic. ----------------------------------
        float r0 = 0.f, r1 = 0.f, r2 = 0.f;
        #pragma unroll
        for (int k = 0; k < 4; ++k) {
            const float4* slot = &g_part4[lane * 4 + k];
            float ax, ay, az, aw;
            do {
                asm volatile("ld.global.cg.v4.f32 {%0,%1,%2,%3}, [%4];"
                             : "=f"(ax), "=f"(ay), "=f"(az), "=f"(aw)
                             : "l"(slot));
            } while (aw == 0.0f);
            r0 += ax; r1 += ay; r2 += az;
        }
        #pragma unroll
        for (int off = 16; off > 0; off >>= 1) {
            r0 += __shfl_down_sync(0xFFFFFFFFu, r0, off);
            r1 += __shfl_down_sync(0xFFFFFFFFu, r1, off);
            r2 += __shfl_down_sync(0xFFFFFFFFu, r2, off);
        }
        r0 = __shfl_sync(0xFFFFFFFFu, r0, 0);
        r1 = __shfl_sync(0xFFFFFFFFu, r1, 0);
        r2 = __shfl_sync(0xFFFFFFFFu, r2, 0);

        // Per-lane head outputs: p0=lane, p1=lane+27 (lanes < 27).
        const int p0 = (lane < 27) ? lane : 0;
        const int j0 = p0 / OUTPUTS, o0 = p0 - j0 * OUTPUTS;   // j0 in {0,1}
        const int p1 = p0 + 27;
        const int j1 = p1 / OUTPUTS, o1 = p1 - j1 * OUTPUTS;   // j1 in {1,2}

        // ---- Layer 0 (all lanes redundantly; no cross-lane dependency) ----
        float h0 = tanh_hw(r0 + sB0[0]);
        float h1 = tanh_hw(r1 + sB0[1]);
        float h2 = tanh_hw(r2 + sB0[2]);

        float acc0 = 0.f, acc1 = 0.f;
        float4 c0 = sP2[0], c1 = sP2[1], c2 = sP2[2];

        // ---- 119 layers. MUFU results arrive staggered (h0 first, h2 ~16cyc
        // later), so the FMA tree consumes h0 INNERMOST: the tree starts the
        // moment h0 lands and h1/h2 slot into later levels just in time.
        // Packing: c0={w00,w01,w02,w10} c1={w11,w12,w20,w21} c2={w22,b0,b1,b2}
        #pragma unroll 7
        for (int l = 1; l <= NCHAIN; ++l) {
            const float4 n0 = sP2[l * 3 + 0];     // next layer (pad-safe)
            const float4 n1 = sP2[l * 3 + 1];
            const float4 n2 = sP2[l * 3 + 2];
            // Head contribution of H[l-1] (current h regs) in the bubble.
            const float ha = (j0 == 0) ? h0 : h1;
            const float hb = (j1 == 1) ? h1 : h2;
            acc0 = fmaf(ha, sWhT[(l - 1) * OUTPUTS + o0], acc0);
            acc1 = fmaf(hb, sWhT[(l - 1) * OUTPUTS + o1], acc1);
            // Chain step: h0 innermost, h2 outermost (latency-ordered).
            const float t0 = fmaf(c0.z, h2, fmaf(c0.y, h1, fmaf(c0.x, h0, c2.y)));
            const float t1 = fmaf(c1.y, h2, fmaf(c1.x, h1, fmaf(c0.w, h0, c2.z)));
            const float t2 = fmaf(c2.x, h2, fmaf(c1.w, h1, fmaf(c1.z, h0, c2.w)));
            h0 = tanh_hw(t0);
            h1 = tanh_hw(t1);
            h2 = tanh_hw(t2);
            c0 = n0; c1 = n1; c2 = n2;
        }

        // ---- Final layer's H into the head, then write -------------------
        const float ha = (j0 == 0) ? h0 : h1;
        const float hb = (j1 == 1) ? h1 : h2;
        acc0 = fmaf(ha, sWhT[NCHAIN * OUTPUTS + o0], acc0);
        acc1 = fmaf(hb, sWhT[NCHAIN * OUTPUTS + o1], acc1);

        if (lane < 27) {
            out[j0 * OUTPUTS + o0] = acc0 + sBh[o0];
            out[j1 * OUTPUTS + o1] = acc1 + sBh[o1];
        }

        // ---- Reset flags for the next graph replay (off critical path;
        //      replays are stream-serialized so no race with producers). ----
        #pragma unroll
        for (int k = 0; k < 4; ++k) {
            float zero = 0.0f;
            asm volatile("st.global.cg.f32 [%0], %1;"
                         :: "l"(reinterpret_cast<char*>(&g_part4[lane * 4 + k]) + 12),
                            "f"(zero) : "memory");
        }
        return;
    }

    // ======================= Producer blocks (bid 1..128) ===================
    const int pid = bid - 1;
    const uint32_t mb = smem_u32(&mbar);

    if (tid == 0) {
        asm volatile("mbarrier.init.shared.b64 [%0], 1;" :: "r"(mb) : "memory");
    }
    __syncthreads();

    if (tid == 0) {
        asm volatile("fence.proxy.async.shared::cta;" ::: "memory");
        asm volatile("mbarrier.arrive.expect_tx.shared.b64 _, [%0], %1;"
                     :: "r"(mb), "r"(4u * CHUNK_BYTES) : "memory");
        const char* srcx = (const char*)x             + (size_t)pid * CHUNK_BYTES;
        const char* s0   = (const char*)W0            + (size_t)pid * CHUNK_BYTES;
        const char* s1   = (const char*)(W0 + N_IN)   + (size_t)pid * CHUNK_BYTES;
        const char* s2   = (const char*)(W0 + 2*N_IN) + (size_t)pid * CHUNK_BYTES;
        asm volatile("cp.async.bulk.shared::cluster.global.mbarrier::complete_tx::bytes [%0], [%1], %2, [%3];"
                     :: "r"(smem_u32(sX)),  "l"(srcx), "r"((uint32_t)CHUNK_BYTES), "r"(mb) : "memory");
        asm volatile("cp.async.bulk.shared::cluster.global.mbarrier::complete_tx::bytes [%0], [%1], %2, [%3];"
                     :: "r"(smem_u32(sW0)), "l"(s0),   "r"((uint32_t)CHUNK_BYTES), "r"(mb) : "memory");
        asm volatile("cp.async.bulk.shared::cluster.global.mbarrier::complete_tx::bytes [%0], [%1], %2, [%3];"
                     :: "r"(smem_u32(sW1)), "l"(s1),   "r"((uint32_t)CHUNK_BYTES), "r"(mb) : "memory");
        asm volatile("cp.async.bulk.shared::cluster.global.mbarrier::complete_tx::bytes [%0], [%1], %2, [%3];"
                     :: "r"(smem_u32(sW2)), "l"(s2),   "r"((uint32_t)CHUNK_BYTES), "r"(mb) : "memory");
    }

    // Wait for the bulk copies (acquire).
    asm volatile(
        "{\n\t"
        ".reg .pred p;\n\t"
        "W%=:\n\t"
        "mbarrier.try_wait.parity.acquire.cta.shared::cta.b64 p, [%0], 0;\n\t"
        "@!p bra W%=;\n\t"
        "}" :: "r"(mb) : "memory");

    // Dot products out of shared (2 positions per thread).
    float s0, s1, s2;
    {
        const int q0 = tid, q1 = tid + THREADS;
        const float4 xa = sX[q0],  xb = sX[q1];
        const float4 a0 = sW0[q0], b0 = sW0[q1];
        const float4 a1 = sW1[q0], b1 = sW1[q1];
        const float4 a2 = sW2[q0], b2 = sW2[q1];
        s0 = a0.x*xa.x + a0.y*xa.y + a0.z*xa.z + a0.w*xa.w
           + b0.x*xb.x + b0.y*xb.y + b0.z*xb.z + b0.w*xb.w;
        s1 = a1.x*xa.x + a1.y*xa.y + a1.z*xa.z + a1.w*xa.w
           + b1.x*xb.x + b1.y*xb.y + b1.z*xb.z + b1.w*xb.w;
        s2 = a2.x*xa.x + a2.y*xa.y + a2.z*xa.z + a2.w*xa.w
           + b2.x*xb.x + b2.y*xb.y + b2.z*xb.z + b2.w*xb.w;
    }
    #pragma unroll
    for (int off = 16; off > 0; off >>= 1) {
        s0 += __shfl_down_sync(0xFFFFFFFFu, s0, off);
        s1 += __shfl_down_sync(0xFFFFFFFFu, s1, off);
        s2 += __shfl_down_sync(0xFFFFFFFFu, s2, off);
    }
    const int wid = tid >> 5, lid = tid & 31;
    if (lid == 0) { wsum[0][wid] = s0; wsum[1][wid] = s1; wsum[2][wid] = s2; }
    __syncthreads();

    if (tid == 0) {
        float b0 = 0.f, b1 = 0.f, b2 = 0.f;
        #pragma unroll
        for (int w = 0; w < 8; ++w) {
            b0 += wsum[0][w]; b1 += wsum[1][w]; b2 += wsum[2][w];
        }
        // Single 16B store: data + flag arrive atomically at L2.
        asm volatile("st.global.cg.v4.f32 [%0], {%1,%2,%3,%4};"
                     :: "l"(&g_part4[pid]),
                        "f"(b0), "f"(b1), "f"(b2), "f"(1.0f) : "memory");
    }
}

extern "C" void kernel_launch(void* const* d_in, const int* in_sizes, int n_in,
                              void* d_out, int out_size) {
    const float* x    = (const float*)d_in[0];
    const float* W0   = (const float*)d_in[1];
    const float* bih0 = (const float*)d_in[2];
    const float* bhh0 = (const float*)d_in[3];
    const float* Wl   = (const float*)d_in[4];
    const float* bil  = (const float*)d_in[5];
    const float* bhl  = (const float*)d_in[6];
    const float* Wh   = (const float*)d_in[7];
    const float* bh   = (const float*)d_in[8];
    float* out        = (float*)d_out;

    dqn_fused_kernel<<<GRID, THREADS>>>(x, W0, bih0, bhh0,
                                        Wl, bil, bhl, Wh, bh, out);
}